// round 12
// baseline (speedup 1.0000x reference)
#include <cuda_runtime.h>
#include <cstdint>

#define NTOK 4096
#define DHID 2048
#define IEXP 8192
#define NE   8
#define G1   64

// ---------------- scratch ----------------
__device__ float g_T[NTOK * G1];
__device__ float g_coef[NTOK * 4];
__device__ float g_X32[(size_t)NTOK * DHID];
__device__ float g_Wg32[(size_t)DHID * IEXP];
__device__ float g_Wu32[(size_t)DHID * IEXP];
__device__ float g_Wd32[(size_t)IEXP * DHID];
__device__ float g_H[(size_t)NTOK * IEXP];

// ---------------- helpers ----------------
__device__ __forceinline__ unsigned f2tf32(float x) {
    unsigned y; asm("cvt.rna.tf32.f32 %0, %1;" : "=r"(y) : "f"(x)); return y;
}
__device__ __forceinline__ float siluf(float z) { return z / (1.0f + __expf(-z)); }
__device__ __forceinline__ uint32_t smem_u32(const void* p) {
    uint32_t a;
    asm("{ .reg .u64 t; cvta.to.shared.u64 t, %1; cvt.u32.u64 %0, t; }" : "=r"(a) : "l"(p));
    return a;
}
__device__ __forceinline__ void cpa16(uint32_t d, const float* s) {
    asm volatile("cp.async.cg.shared.global [%0], [%1], 16;" :: "r"(d), "l"(s));
}
#define CPA_COMMIT() asm volatile("cp.async.commit_group;" ::: "memory")
#define CPA_WAIT(n)  asm volatile("cp.async.wait_group %0;" :: "n"(n) : "memory")

#define MMA_TF32(c, a, b)                                                        \
    asm volatile(                                                                \
        "mma.sync.aligned.m16n8k8.row.col.f32.tf32.tf32.f32 "                    \
        "{%0,%1,%2,%3}, {%4,%5,%6,%7}, {%8,%9}, {%0,%1,%2,%3};"                  \
        : "+f"((c)[0]), "+f"((c)[1]), "+f"((c)[2]), "+f"((c)[3])                 \
        : "r"((a)[0]), "r"((a)[1]), "r"((a)[2]), "r"((a)[3]),                    \
          "r"((b)[0]), "r"((b)[1]))

// per stage (floats): A 256x36 = 9216, B 32x136 = 4352 -> 13568
#define OFF_A(s) ((s) * 13568)
#define OFF_B(s) ((s) * 13568 + 9216)
#define SMEM_BYTES (3 * 13568 * 4)   // 162816 bytes, 3 stages, 1 CTA/SM

// ======================================================================
// Prep: elementwise tf32 rounding
// ======================================================================
__global__ __launch_bounds__(256) void round_tf32_k(
    const float* __restrict__ src, float* __restrict__ dst, int n4)
{
    int i = blockIdx.x * blockDim.x + threadIdx.x;
    int stride = gridDim.x * blockDim.x;
    for (; i < n4; i += stride) {
        float4 v = ((const float4*)src)[i];
        v.x = __uint_as_float(f2tf32(v.x)); v.y = __uint_as_float(f2tf32(v.y));
        v.z = __uint_as_float(f2tf32(v.z)); v.w = __uint_as_float(f2tf32(v.w));
        ((float4*)dst)[i] = v;
    }
}

// ======================================================================
// Router stage A: T = tanh(X @ gate_w1)
// ======================================================================
__global__ __launch_bounds__(256) void router_gemm_tanh(
    const float* __restrict__ X, const float* __restrict__ W1)
{
    __shared__ float Xs[32][65];
    __shared__ float Ws[32][64];
    const int tid = threadIdx.x;
    const int tx = tid & 15, ty = tid >> 4;
    const int m0 = blockIdx.x * 64;

    float acc[4][4] = {};
    for (int k0 = 0; k0 < DHID; k0 += 32) {
        __syncthreads();
        #pragma unroll
        for (int i = 0; i < 8; i++) {
            int e = tid + i * 256;
            Xs[e & 31][e >> 5] = X[(size_t)(m0 + (e >> 5)) * DHID + k0 + (e & 31)];
        }
        #pragma unroll
        for (int i = 0; i < 8; i++) {
            int e = tid + i * 256;
            Ws[e >> 6][e & 63] = W1[(size_t)(k0 + (e >> 6)) * G1 + (e & 63)];
        }
        __syncthreads();
        #pragma unroll
        for (int k = 0; k < 32; k++) {
            float av[4], bv[4];
            #pragma unroll
            for (int i = 0; i < 4; i++) av[i] = Xs[k][ty * 4 + i];
            #pragma unroll
            for (int j = 0; j < 4; j++) bv[j] = Ws[k][tx * 4 + j];
            #pragma unroll
            for (int i = 0; i < 4; i++)
                #pragma unroll
                for (int j = 0; j < 4; j++)
                    acc[i][j] = fmaf(av[i], bv[j], acc[i][j]);
        }
    }
    #pragma unroll
    for (int i = 0; i < 4; i++)
        #pragma unroll
        for (int j = 0; j < 4; j++)
            g_T[(size_t)(m0 + ty * 4 + i) * G1 + tx * 4 + j] = tanhf(acc[i][j]);
}

// ======================================================================
// Router stage B
// ======================================================================
__global__ __launch_bounds__(128) void router_combine(
    const float* __restrict__ X, const float* __restrict__ W2,
    const float* __restrict__ ceWg, float* __restrict__ logits_out)
{
    const int n = blockIdx.x;
    const int tid = threadIdx.x;
    __shared__ float red[4][128];
    __shared__ float lg[8];

    float pg0 = 0.f, pg1 = 0.f, pg2 = 0.f, pg3 = 0.f;
    for (int k = tid; k < DHID; k += 128) {
        float xv = X[(size_t)n * DHID + k];
        pg0 = fmaf(xv, ceWg[k * 2 + 0], pg0);
        pg1 = fmaf(xv, ceWg[k * 2 + 1], pg1);
        pg2 = fmaf(xv, ceWg[DHID * 2 + k * 2 + 0], pg2);
        pg3 = fmaf(xv, ceWg[DHID * 2 + k * 2 + 1], pg3);
    }
    red[0][tid] = pg0; red[1][tid] = pg1; red[2][tid] = pg2; red[3][tid] = pg3;
    __syncthreads();
    for (int s = 64; s > 0; s >>= 1) {
        if (tid < s) {
            #pragma unroll
            for (int j = 0; j < 4; j++) red[j][tid] += red[j][tid + s];
        }
        __syncthreads();
    }
    if (tid < NE) {
        float s = 0.f;
        #pragma unroll 8
        for (int i = 0; i < G1; i++)
            s = fmaf(g_T[(size_t)n * G1 + i], W2[i * NE + tid], s);
        lg[tid] = s;
        logits_out[(size_t)n * NE + tid] = s;
    }
    __syncthreads();
    if (tid == 0) {
        float p[NE];
        float mx = lg[0];
        #pragma unroll
        for (int e = 1; e < NE; e++) mx = fmaxf(mx, lg[e]);
        float sum = 0.f;
        #pragma unroll
        for (int e = 0; e < NE; e++) { p[e] = __expf(lg[e] - mx); sum += p[e]; }
        float inv = 1.f / sum;
        #pragma unroll
        for (int e = 0; e < NE; e++) p[e] *= inv;
        int i0 = 0;
        #pragma unroll
        for (int e = 1; e < NE; e++) if (p[e] > p[i0]) i0 = e;
        int i1 = (i0 == 0) ? 1 : 0;
        #pragma unroll
        for (int e = 0; e < NE; e++) if (e != i0 && p[e] > p[i1]) i1 = e;
        float w0 = (i0 == NE - 1) ? 0.f : p[i0];
        float w1 = (i1 == NE - 1) ? 0.f : p[i1];
        float winv = 1.f / (w0 + w1);
        w0 *= winv; w1 *= winv;
        float pe[NE];
        #pragma unroll
        for (int e = 0; e < NE; e++) pe[e] = 0.f;
        pe[i0] += w0; pe[i1] += w1;
        float cw0x = 1.f / (1.f + __expf(red[1][0] - red[0][0]));
        float cw1x = 1.f / (1.f + __expf(red[3][0] - red[2][0]));
        g_coef[n * 4 + 0] = pe[0] + pe[2] * cw0x + pe[3] * cw1x;
        g_coef[n * 4 + 1] = pe[2] * (1.f - cw0x);
        g_coef[n * 4 + 2] = pe[3] * (1.f - cw1x);
        g_coef[n * 4 + 3] = pe[4] + pe[5] + pe[6] + pe[7];
    }
}

// ======================================================================
// GEMM 1: H = silu(X@Wg) * (X@Wu)
// CTA: 256 threads (8 warps, 4x2), CTA tile M=256 x mmaN=128 (G|U 64 each).
// Warp tile m64 x n64. 3-stage cp.async, one barrier per k-tile.
// ======================================================================
__global__ __launch_bounds__(256, 1) void gemm_gateup()
{
    extern __shared__ unsigned sm[];
    const uint32_t sa = smem_u32(sm);
    const int tid = threadIdx.x;
    const int lane = tid & 31, wid = tid >> 5;
    const int wm = wid & 3, wn = wid >> 2;          // 4x2
    const int g = lane >> 2, tg = lane & 3;
    const int m0 = blockIdx.x * 256;
    const int n0 = blockIdx.y * 64;
    const int KT = DHID / 32;

    float acc[4][8][4] = {};

    auto issue = [&](int kt) {
        int s = kt % 3, k0 = kt * 32;
        #pragma unroll
        for (int i = 0; i < 8; i++) {                 // A: 256x32
            int e = tid + i * 256;
            int r = e >> 3, q = e & 7;
            cpa16(sa + (OFF_A(s) + r * 36 + q * 4) * 4,
                  g_X32 + (size_t)(m0 + r) * DHID + k0 + q * 4);
        }
        #pragma unroll
        for (int i = 0; i < 4; i++) {                 // B: 32x128 (Wg|Wu)
            int e = tid + i * 256;
            int kk = e >> 5, c8 = e & 31;
            const float* src = (c8 < 16)
                ? g_Wg32 + (size_t)(k0 + kk) * IEXP + n0 + c8 * 4
                : g_Wu32 + (size_t)(k0 + kk) * IEXP + n0 + (c8 - 16) * 4;
            cpa16(sa + (OFF_B(s) + kk * 136 + c8 * 4) * 4, src);
        }
        CPA_COMMIT();
    };

    issue(0); issue(1);
    const int arow = wm * 64;
    const int bcol = wn * 64;

    for (int kt = 0; kt < KT; kt++) {
        if (kt < KT - 1) CPA_WAIT(1); else CPA_WAIT(0);
        __syncthreads();
        if (kt + 2 < KT) issue(kt + 2);
        const unsigned* As = sm + OFF_A(kt % 3);
        const unsigned* Bs = sm + OFF_B(kt % 3);
        #pragma unroll
        for (int ks = 0; ks < 4; ks++) {
            int c = ks * 8 + tg;
            unsigned a[4][4];
            #pragma unroll
            for (int mi = 0; mi < 4; mi++) {
                int r = arow + mi * 16 + g;
                a[mi][0] = As[r * 36 + c];
                a[mi][1] = As[(r + 8) * 36 + c];
                a[mi][2] = As[r * 36 + c + 4];
                a[mi][3] = As[(r + 8) * 36 + c + 4];
            }
            unsigned b[8][2];
            #pragma unroll
            for (int ni = 0; ni < 8; ni++) {
                int nn = bcol + ni * 8 + g;
                b[ni][0] = Bs[c * 136 + nn];
                b[ni][1] = Bs[(c + 4) * 136 + nn];
            }
            #pragma unroll
            for (int mi = 0; mi < 4; mi++)
                #pragma unroll
                for (int ni = 0; ni < 8; ni++)
                    MMA_TF32(acc[mi][ni], a[mi], b[ni]);
        }
    }
    __syncthreads();   // all warps done before smem reuse

    // epilogue: acc -> smem [256][132], pair G/U, write g_H (tf32-rounded)
    float* Hs = (float*)sm;
    #pragma unroll
    for (int mi = 0; mi < 4; mi++) {
        int r1 = arow + mi * 16 + g, r2 = r1 + 8;
        #pragma unroll
        for (int ni = 0; ni < 8; ni++) {
            int cc = bcol + ni * 8 + 2 * tg;
            float* c = acc[mi][ni];
            *(float2*)(Hs + r1 * 132 + cc) = make_float2(c[0], c[1]);
            *(float2*)(Hs + r2 * 132 + cc) = make_float2(c[2], c[3]);
        }
    }
    __syncthreads();
    #pragma unroll
    for (int i = 0; i < 64; i++) {
        int e = tid + i * 256;
        int r = e >> 6, cc = e & 63;
        float gv = Hs[r * 132 + cc];
        float uv = Hs[r * 132 + 64 + cc];
        g_H[(size_t)(m0 + r) * IEXP + n0 + cc] = __uint_as_float(f2tf32(siluf(gv) * uv));
    }
}

// ======================================================================
// GEMM 2: out = cs*(H@Wd) + cx*x + cc0*c0 + cc1*c1
// CTA: 256 threads (8 warps, 4x2), tile M=256 x N=128. Warp tile m64xn64.
// 3-stage cp.async.
// ======================================================================
__global__ __launch_bounds__(256, 1) void gemm_down(
    const float* __restrict__ X,
    const float* __restrict__ ceC,
    float* __restrict__ out)
{
    extern __shared__ unsigned sm[];
    const uint32_t sa = smem_u32(sm);
    const int tid = threadIdx.x;
    const int lane = tid & 31, wid = tid >> 5;
    const int wm = wid & 3, wn = wid >> 2;
    const int g = lane >> 2, tg = lane & 3;
    const int m0 = blockIdx.x * 256;
    const int n0 = blockIdx.y * 128;
    const int KT = IEXP / 32;

    float acc[4][8][4] = {};

    auto issue = [&](int kt) {
        int s = kt % 3, k0 = kt * 32;
        #pragma unroll
        for (int i = 0; i < 8; i++) {                 // A from g_H: 256x32
            int e = tid + i * 256;
            int r = e >> 3, q = e & 7;
            cpa16(sa + (OFF_A(s) + r * 36 + q * 4) * 4,
                  g_H + (size_t)(m0 + r) * IEXP + k0 + q * 4);
        }
        #pragma unroll
        for (int i = 0; i < 4; i++) {                 // B: Wd 32x128
            int e = tid + i * 256;
            int kk = e >> 5, c8 = e & 31;
            cpa16(sa + (OFF_B(s) + kk * 136 + c8 * 4) * 4,
                  g_Wd32 + (size_t)(k0 + kk) * DHID + n0 + c8 * 4);
        }
        CPA_COMMIT();
    };

    issue(0); issue(1);
    const int arow = wm * 64;
    const int bcol = wn * 64;

    for (int kt = 0; kt < KT; kt++) {
        if (kt < KT - 1) CPA_WAIT(1); else CPA_WAIT(0);
        __syncthreads();
        if (kt + 2 < KT) issue(kt + 2);
        const unsigned* As = sm + OFF_A(kt % 3);
        const unsigned* Bs = sm + OFF_B(kt % 3);
        #pragma unroll
        for (int ks = 0; ks < 4; ks++) {
            int c = ks * 8 + tg;
            unsigned a[4][4];
            #pragma unroll
            for (int mi = 0; mi < 4; mi++) {
                int r = arow + mi * 16 + g;
                a[mi][0] = As[r * 36 + c];
                a[mi][1] = As[(r + 8) * 36 + c];
                a[mi][2] = As[r * 36 + c + 4];
                a[mi][3] = As[(r + 8) * 36 + c + 4];
            }
            unsigned b[8][2];
            #pragma unroll
            for (int ni = 0; ni < 8; ni++) {
                int nn = bcol + ni * 8 + g;
                b[ni][0] = Bs[c * 136 + nn];
                b[ni][1] = Bs[(c + 4) * 136 + nn];
            }
            #pragma unroll
            for (int mi = 0; mi < 4; mi++)
                #pragma unroll
                for (int ni = 0; ni < 8; ni++)
                    MMA_TF32(acc[mi][ni], a[mi], b[ni]);
        }
    }

    // epilogue: fold routing coefficients, direct from regs
    const float* c0 = ceC;
    const float* c1 = ceC + DHID;
    #pragma unroll
    for (int mi = 0; mi < 4; mi++) {
        int r1 = m0 + arow + mi * 16 + g;
        int r2 = r1 + 8;
        float cx1 = g_coef[r1 * 4 + 0], cc01 = g_coef[r1 * 4 + 1],
              cc11 = g_coef[r1 * 4 + 2], cs1 = g_coef[r1 * 4 + 3];
        float cx2 = g_coef[r2 * 4 + 0], cc02 = g_coef[r2 * 4 + 1],
              cc12 = g_coef[r2 * 4 + 2], cs2 = g_coef[r2 * 4 + 3];
        #pragma unroll
        for (int ni = 0; ni < 8; ni++) {
            int nn = n0 + bcol + ni * 8 + 2 * tg;
            float* c = acc[mi][ni];
            float2 x1 = *(const float2*)(X + (size_t)r1 * DHID + nn);
            float2 x2 = *(const float2*)(X + (size_t)r2 * DHID + nn);
            float2 v0 = *(const float2*)(c0 + nn);
            float2 v1 = *(const float2*)(c1 + nn);
            float2 o1, o2;
            o1.x = cs1 * c[0] + cx1 * x1.x + cc01 * v0.x + cc11 * v1.x;
            o1.y = cs1 * c[1] + cx1 * x1.y + cc01 * v0.y + cc11 * v1.y;
            o2.x = cs2 * c[2] + cx2 * x2.x + cc02 * v0.x + cc12 * v1.x;
            o2.y = cs2 * c[3] + cx2 * x2.y + cc02 * v0.y + cc12 * v1.y;
            *(float2*)(out + (size_t)r1 * DHID + nn) = o1;
            *(float2*)(out + (size_t)r2 * DHID + nn) = o2;
        }
    }
}

// ======================================================================
extern "C" void kernel_launch(void* const* d_in, const int* in_sizes, int n_in,
                              void* d_out, int out_size)
{
    const float* X    = (const float*)d_in[0];
    const float* W1   = (const float*)d_in[1];
    const float* W2   = (const float*)d_in[2];
    const float* ceWg = (const float*)d_in[3];
    const float* ceC  = (const float*)d_in[4];
    const float* Wg   = (const float*)d_in[5];
    const float* Wu   = (const float*)d_in[6];
    const float* Wd   = (const float*)d_in[7];
    float* out = (float*)d_out;
    float* logits = out + (size_t)NTOK * DHID;

    cudaFuncSetAttribute(gemm_gateup, cudaFuncAttributeMaxDynamicSharedMemorySize, SMEM_BYTES);
    cudaFuncSetAttribute(gemm_down, cudaFuncAttributeMaxDynamicSharedMemorySize, SMEM_BYTES);

    float *pX32, *pWg32, *pWu32, *pWd32;
    cudaGetSymbolAddress((void**)&pX32, g_X32);
    cudaGetSymbolAddress((void**)&pWg32, g_Wg32);
    cudaGetSymbolAddress((void**)&pWu32, g_Wu32);
    cudaGetSymbolAddress((void**)&pWd32, g_Wd32);

    round_tf32_k<<<1024, 256>>>(X,  pX32,  NTOK * DHID / 4);    // 0
    round_tf32_k<<<2048, 256>>>(Wg, pWg32, DHID * IEXP / 4);    // 1
    round_tf32_k<<<2048, 256>>>(Wu, pWu32, DHID * IEXP / 4);    // 2
    round_tf32_k<<<2048, 256>>>(Wd, pWd32, IEXP * DHID / 4);    // 3
    router_gemm_tanh<<<NTOK / 64, 256>>>(X, W1);                // 4
    gemm_gateup<<<dim3(NTOK / 256, IEXP / 64), 256, SMEM_BYTES>>>();  // 5
    router_combine<<<NTOK, 128>>>(X, W2, ceWg, logits);         // 6
    gemm_down<<<dim3(NTOK / 256, DHID / 128), 256, SMEM_BYTES>>>(X, ceC, out);  // 7
}